// round 3
// baseline (speedup 1.0000x reference)
#include <cuda_runtime.h>
#include <math.h>

#define NTOK 4096
#define DDIM 1024
#define SDIM 16
#define NEXP 4
#define HDIM 2048
#define LSEQ 2048

typedef unsigned long long u64;

// ---------------- scratch (static device globals; no allocation) ----------------
__device__ float g_delta[NTOK * DDIM];
__device__ float g_Bm[NTOK * SDIM];
__device__ float g_Cm[NTOK * SDIM];
__device__ float g_ssm[NTOK * DDIM];
__device__ float g_moe[NTOK * DDIM];
__device__ float g_G[NTOK * HDIM];
__device__ int   g_cnt[NEXP];
__device__ int   g_list[NEXP * NTOK];
__device__ float g_wgt[NEXP * NTOK];

// ---------------- helpers ----------------
__device__ __forceinline__ void ffma2(u64& d, u64 a, u64 b) {
    // packed (lo,hi) fused multiply-add: d = a*b + d elementwise, exact IEEE fma x2
    asm("fma.rn.f32x2 %0, %1, %2, %0;" : "+l"(d) : "l"(a), "l"(b));
}
__device__ __forceinline__ float2 unpk(u64 v) {
    float2 r;
    asm("mov.b64 {%0, %1}, %2;" : "=f"(r.x), "=f"(r.y) : "l"(v));
    return r;
}

__device__ __forceinline__ float softplusf(float z) {
    return fmaxf(z, 0.f) + log1pf(__expf(-fabsf(z)));
}

__device__ __forceinline__ float blockReduceSum(float v) {
    __shared__ float sh[9];
    int lane = threadIdx.x & 31, wid = threadIdx.x >> 5;
#pragma unroll
    for (int o = 16; o > 0; o >>= 1) v += __shfl_xor_sync(0xffffffffu, v, o);
    if (lane == 0) sh[wid] = v;
    __syncthreads();
    if (wid == 0) {
        float t = (lane < 8) ? sh[lane] : 0.f;
#pragma unroll
        for (int o = 4; o > 0; o >>= 1) t += __shfl_xor_sync(0xffffffffu, t, o);
        if (lane == 0) sh[8] = t;
    }
    __syncthreads();
    return sh[8];
}

// ---------------- zero moe + counts ----------------
__global__ void k_zero() {
    int i = blockIdx.x * blockDim.x + threadIdx.x;
    int stride = gridDim.x * blockDim.x;
    for (int j = i; j < NTOK * DDIM; j += stride) g_moe[j] = 0.f;
    if (i < NEXP) g_cnt[i] = 0;
}

// Duplicate-store a float4 of B values into a pair-duplicated smem row:
// dst[0..7] = {v.x,v.x, v.y,v.y, v.z,v.z, v.w,v.w}
__device__ __forceinline__ void storeDup(float* dst, float4 v) {
    float4 lo = make_float4(v.x, v.x, v.y, v.y);
    float4 hi = make_float4(v.z, v.z, v.w, v.w);
    *(float4*)(dst)     = lo;
    *(float4*)(dst + 4) = hi;
}

// ---------------- delta GEMM: softplus(x @ W_delta + b), FFMA2 core ----------------
// BM=128, BN=64, BK=16, 256 threads, per-thread 8 rows (4 pairs) x 4 cols
__global__ void __launch_bounds__(256) k_delta(const float* __restrict__ x,
                                               const float* __restrict__ Wd,
                                               const float* __restrict__ bd) {
    const int K = DDIM, N = DDIM;
    __shared__ float As[16][128];
    __shared__ float Bs2[16][128];   // duplicated pairs: col c at [2c],[2c+1]
    int tid = threadIdx.x;
    int rowBase = blockIdx.x * 128, colBase = blockIdx.y * 64;
    int ar = tid >> 1, ak = (tid & 1) * 8;
    int br = tid >> 4, bc = (tid & 15) * 4;
    int ty = tid >> 4, tx = tid & 15;
    const float* Arow = x + (size_t)(rowBase + ar) * K;
    u64 acc[4][4] = {};
    for (int k0 = 0; k0 < K; k0 += 16) {
        float4 a0 = *(const float4*)(Arow + k0 + ak);
        float4 a1 = *(const float4*)(Arow + k0 + ak + 4);
        As[ak + 0][ar] = a0.x; As[ak + 1][ar] = a0.y; As[ak + 2][ar] = a0.z; As[ak + 3][ar] = a0.w;
        As[ak + 4][ar] = a1.x; As[ak + 5][ar] = a1.y; As[ak + 6][ar] = a1.z; As[ak + 7][ar] = a1.w;
        storeDup(&Bs2[br][bc * 2], *(const float4*)(Wd + (size_t)(k0 + br) * N + colBase + bc));
        __syncthreads();
#pragma unroll
        for (int kk = 0; kk < 16; kk++) {
            ulonglong2 ap0 = *(const ulonglong2*)&As[kk][ty * 8];
            ulonglong2 ap1 = *(const ulonglong2*)&As[kk][ty * 8 + 4];
            ulonglong2 bd0 = *(const ulonglong2*)&Bs2[kk][tx * 8];
            ulonglong2 bd1 = *(const ulonglong2*)&Bs2[kk][tx * 8 + 4];
            u64 ap[4] = {ap0.x, ap0.y, ap1.x, ap1.y};
            u64 bp[4] = {bd0.x, bd0.y, bd1.x, bd1.y};
#pragma unroll
            for (int i = 0; i < 4; i++)
#pragma unroll
                for (int j = 0; j < 4; j++) ffma2(acc[i][j], ap[i], bp[j]);
        }
        __syncthreads();
    }
#pragma unroll
    for (int i = 0; i < 4; i++) {
#pragma unroll
        for (int j = 0; j < 4; j++) {
            float2 v = unpk(acc[i][j]);
            int c = colBase + tx * 4 + j;
            int r0 = rowBase + ty * 8 + 2 * i;
            float bb = bd[c];
            g_delta[(size_t)r0 * N + c]       = softplusf(v.x + bb);
            g_delta[(size_t)(r0 + 1) * N + c] = softplusf(v.y + bb);
        }
    }
}

// ---------------- Bm / Cm: skinny GEMM, one warp per token ----------------
__global__ void k_bc(const float* __restrict__ x, const float* __restrict__ WB,
                     const float* __restrict__ WC) {
    int wid = (blockIdx.x * blockDim.x + threadIdx.x) >> 5;
    int lane = threadIdx.x & 31;
    if (wid >= NTOK) return;
    const float* W = (lane < 16) ? WB : WC;
    int col = lane & 15;
    const float* xr = x + (size_t)wid * DDIM;
    float acc = 0.f;
#pragma unroll 8
    for (int k = 0; k < DDIM; k++) acc = fmaf(xr[k], W[k * SDIM + col], acc);
    if (lane < 16) g_Bm[wid * SDIM + col] = acc;
    else           g_Cm[wid * SDIM + col] = acc;
}

// ---------------- selective scan: 16 lanes (states) per (b,d) channel ----------------
__global__ void k_scan(const float* __restrict__ x, const float* __restrict__ A_log,
                       const float* __restrict__ Dp) {
    int tid = threadIdx.x;
    int grp = tid >> 4, s = tid & 15;
    int c = blockIdx.x * 16 + grp;
    int b = c >> 10, d = c & 1023;
    float a = -__expf(A_log[d * SDIM + s]);
    float dpar = Dp[d];
    float h = 0.f;
    const float* xb = x + (size_t)b * LSEQ * DDIM + d;
    const float* db = g_delta + (size_t)b * LSEQ * DDIM + d;
    const float* Bb = g_Bm + (size_t)b * LSEQ * SDIM + s;
    const float* Cb = g_Cm + (size_t)b * LSEQ * SDIM + s;
    float* yb = g_ssm + (size_t)b * LSEQ * DDIM + d;
#pragma unroll 4
    for (int t = 0; t < LSEQ; t++) {
        float dv = db[(size_t)t * DDIM];
        float xv = xb[(size_t)t * DDIM];
        float Bv = Bb[t * SDIM];
        float Cv = Cb[t * SDIM];
        float barA = __expf(fminf(dv * a, 10.f));
        float barB = fminf(fmaxf(dv * Bv, -10.f), 10.f);
        h = fminf(fmaxf(fmaf(barA, h, barB * xv), -10000.f), 10000.f);
        float p = h * Cv;
        p += __shfl_xor_sync(0xffffffffu, p, 8);
        p += __shfl_xor_sync(0xffffffffu, p, 4);
        p += __shfl_xor_sync(0xffffffffu, p, 2);
        p += __shfl_xor_sync(0xffffffffu, p, 1);
        if (s == 0) yb[(size_t)t * DDIM] = p + xv * dpar;
    }
}

// ---------------- router: softmax over E=4, top-2, build per-expert lists ----------------
__global__ void k_router(const float* __restrict__ Wr) {
    int wid = (blockIdx.x * blockDim.x + threadIdx.x) >> 5;
    int lane = threadIdx.x & 31;
    if (wid >= NTOK) return;
    const float* xr = g_ssm + (size_t)wid * DDIM;
    float l[4] = {0.f, 0.f, 0.f, 0.f};
    for (int k = lane; k < DDIM; k += 32) {
        float xv = xr[k];
        float4 w = *(const float4*)(Wr + (size_t)k * 4);
        l[0] = fmaf(xv, w.x, l[0]);
        l[1] = fmaf(xv, w.y, l[1]);
        l[2] = fmaf(xv, w.z, l[2]);
        l[3] = fmaf(xv, w.w, l[3]);
    }
#pragma unroll
    for (int e = 0; e < 4; e++)
#pragma unroll
        for (int o = 16; o > 0; o >>= 1) l[e] += __shfl_xor_sync(0xffffffffu, l[e], o);
    if (lane == 0) {
        float m = fmaxf(fmaxf(l[0], l[1]), fmaxf(l[2], l[3]));
        float p[4]; float ssum = 0.f;
#pragma unroll
        for (int e = 0; e < 4; e++) { p[e] = __expf(l[e] - m); ssum += p[e]; }
#pragma unroll
        for (int e = 0; e < 4; e++) p[e] /= ssum;
        int e1 = 0; float b1 = p[0];
#pragma unroll
        for (int e = 1; e < 4; e++) if (p[e] > b1) { b1 = p[e]; e1 = e; }
        int e2 = -1; float b2 = -1.f;
#pragma unroll
        for (int e = 0; e < 4; e++) if (e != e1 && p[e] > b2) { b2 = p[e]; e2 = e; }
        float wsum = b1 + b2 + 1e-9f;
        float w1 = b1 / wsum, w2 = b2 / wsum;
        int pos1 = atomicAdd(&g_cnt[e1], 1);
        g_list[e1 * NTOK + pos1] = wid; g_wgt[e1 * NTOK + pos1] = w1;
        int pos2 = atomicAdd(&g_cnt[e2], 1);
        g_list[e2 * NTOK + pos2] = wid; g_wgt[e2 * NTOK + pos2] = w2;
    }
}

// ---------------- fused gate+up GEMM (gathered rows), FFMA2 core ----------------
__global__ void __launch_bounds__(256) k_gu(int e, const float* __restrict__ Wg_all,
                                            const float* __restrict__ Wu_all) {
    int cnt = g_cnt[e];
    int rowBase = blockIdx.x * 128;
    if (rowBase >= cnt) return;
    const float* Bg = Wg_all + (size_t)e * DDIM * HDIM;
    const float* Bu = Wu_all + (size_t)e * DDIM * HDIM;
    int colBase = blockIdx.y * 64;
    __shared__ float As[16][128];
    __shared__ float Bgs2[16][128];
    __shared__ float Bus2[16][128];
    int tid = threadIdx.x;
    int ar = tid >> 1, ak = (tid & 1) * 8;
    int br = tid >> 4, bc = (tid & 15) * 4;
    int ty = tid >> 4, tx = tid & 15;
    int grow = rowBase + ar;
    int srcRow = (grow < cnt) ? g_list[e * NTOK + grow] : g_list[e * NTOK];
    const float* Arow = g_ssm + (size_t)srcRow * DDIM;
    u64 accg[4][4] = {}, accu[4][4] = {};
    for (int k0 = 0; k0 < DDIM; k0 += 16) {
        float4 a0 = *(const float4*)(Arow + k0 + ak);
        float4 a1 = *(const float4*)(Arow + k0 + ak + 4);
        As[ak + 0][ar] = a0.x; As[ak + 1][ar] = a0.y; As[ak + 2][ar] = a0.z; As[ak + 3][ar] = a0.w;
        As[ak + 4][ar] = a1.x; As[ak + 5][ar] = a1.y; As[ak + 6][ar] = a1.z; As[ak + 7][ar] = a1.w;
        storeDup(&Bgs2[br][bc * 2], *(const float4*)(Bg + (size_t)(k0 + br) * HDIM + colBase + bc));
        storeDup(&Bus2[br][bc * 2], *(const float4*)(Bu + (size_t)(k0 + br) * HDIM + colBase + bc));
        __syncthreads();
#pragma unroll
        for (int kk = 0; kk < 16; kk++) {
            ulonglong2 ap0 = *(const ulonglong2*)&As[kk][ty * 8];
            ulonglong2 ap1 = *(const ulonglong2*)&As[kk][ty * 8 + 4];
            ulonglong2 bg0 = *(const ulonglong2*)&Bgs2[kk][tx * 8];
            ulonglong2 bg1 = *(const ulonglong2*)&Bgs2[kk][tx * 8 + 4];
            ulonglong2 bu0 = *(const ulonglong2*)&Bus2[kk][tx * 8];
            ulonglong2 bu1 = *(const ulonglong2*)&Bus2[kk][tx * 8 + 4];
            u64 ap[4] = {ap0.x, ap0.y, ap1.x, ap1.y};
            u64 bgp[4] = {bg0.x, bg0.y, bg1.x, bg1.y};
            u64 bup[4] = {bu0.x, bu0.y, bu1.x, bu1.y};
#pragma unroll
            for (int i = 0; i < 4; i++)
#pragma unroll
                for (int j = 0; j < 4; j++) {
                    ffma2(accg[i][j], ap[i], bgp[j]);
                    ffma2(accu[i][j], ap[i], bup[j]);
                }
        }
        __syncthreads();
    }
#pragma unroll
    for (int i = 0; i < 4; i++) {
#pragma unroll
        for (int j = 0; j < 4; j++) {
            float2 gv = unpk(accg[i][j]);
            float2 uv = unpk(accu[i][j]);
            int cidx = colBase + tx * 4 + j;
            int r0 = rowBase + ty * 8 + 2 * i;
            if (r0 < cnt) {
                float s0 = 1.f / (1.f + __expf(-gv.x));
                g_G[(size_t)r0 * HDIM + cidx] = gv.x * s0 * uv.x;
            }
            if (r0 + 1 < cnt) {
                float s1 = 1.f / (1.f + __expf(-gv.y));
                g_G[(size_t)(r0 + 1) * HDIM + cidx] = gv.y * s1 * uv.y;
            }
        }
    }
}

// ---------------- rmsnorm over expert hidden rows ----------------
__global__ void k_rmsg(int e, const float* __restrict__ wn) {
    int m = blockIdx.x;
    if (m >= g_cnt[e]) return;
    float* row = g_G + (size_t)m * HDIM;
    const float* w = wn + (size_t)e * HDIM;
    float v[8]; float ss = 0.f;
#pragma unroll
    for (int i = 0; i < 8; i++) {
        v[i] = row[threadIdx.x + i * 256];
        ss += v[i] * v[i];
    }
    ss = blockReduceSum(ss);
    float inv = 1.f / sqrtf(ss * (1.f / HDIM) + 1e-6f);
#pragma unroll
    for (int i = 0; i < 8; i++)
        row[threadIdx.x + i * 256] = w[threadIdx.x + i * 256] * v[i] * inv;
}

// ---------------- down GEMM + weighted scatter-add, FFMA2 core ----------------
__global__ void __launch_bounds__(256) k_down(int e, const float* __restrict__ Wd_all) {
    int cnt = g_cnt[e];
    int rowBase = blockIdx.x * 128;
    if (rowBase >= cnt) return;
    const float* Bd = Wd_all + (size_t)e * HDIM * DDIM;
    int colBase = blockIdx.y * 64;
    __shared__ float As[16][128];
    __shared__ float Bs2[16][128];
    int tid = threadIdx.x;
    int ar = tid >> 1, ak = (tid & 1) * 8;
    int br = tid >> 4, bc = (tid & 15) * 4;
    int ty = tid >> 4, tx = tid & 15;
    const float* Arow = g_G + (size_t)(rowBase + ar) * HDIM;
    u64 acc[4][4] = {};
    for (int k0 = 0; k0 < HDIM; k0 += 16) {
        float4 a0 = *(const float4*)(Arow + k0 + ak);
        float4 a1 = *(const float4*)(Arow + k0 + ak + 4);
        As[ak + 0][ar] = a0.x; As[ak + 1][ar] = a0.y; As[ak + 2][ar] = a0.z; As[ak + 3][ar] = a0.w;
        As[ak + 4][ar] = a1.x; As[ak + 5][ar] = a1.y; As[ak + 6][ar] = a1.z; As[ak + 7][ar] = a1.w;
        storeDup(&Bs2[br][bc * 2], *(const float4*)(Bd + (size_t)(k0 + br) * DDIM + colBase + bc));
        __syncthreads();
#pragma unroll
        for (int kk = 0; kk < 16; kk++) {
            ulonglong2 ap0 = *(const ulonglong2*)&As[kk][ty * 8];
            ulonglong2 ap1 = *(const ulonglong2*)&As[kk][ty * 8 + 4];
            ulonglong2 bd0 = *(const ulonglong2*)&Bs2[kk][tx * 8];
            ulonglong2 bd1 = *(const ulonglong2*)&Bs2[kk][tx * 8 + 4];
            u64 ap[4] = {ap0.x, ap0.y, ap1.x, ap1.y};
            u64 bp[4] = {bd0.x, bd0.y, bd1.x, bd1.y};
#pragma unroll
            for (int i = 0; i < 4; i++)
#pragma unroll
                for (int j = 0; j < 4; j++) ffma2(acc[i][j], ap[i], bp[j]);
        }
        __syncthreads();
    }
#pragma unroll
    for (int i = 0; i < 4; i++) {
        int r0 = rowBase + ty * 8 + 2 * i;
#pragma unroll
        for (int j = 0; j < 4; j++) {
            float2 v = unpk(acc[i][j]);
            int cidx = colBase + tx * 4 + j;
            if (r0 < cnt) {
                int tok = g_list[e * NTOK + r0];
                float w = g_wgt[e * NTOK + r0];
                g_moe[(size_t)tok * DDIM + cidx] += w * v.x;
            }
            if (r0 + 1 < cnt) {
                int tok = g_list[e * NTOK + r0 + 1];
                float w = g_wgt[e * NTOK + r0 + 1];
                g_moe[(size_t)tok * DDIM + cidx] += w * v.y;
            }
        }
    }
}

// ---------------- final rmsnorm(ssm + moe) ----------------
__global__ void k_final(const float* __restrict__ nw, float* __restrict__ out) {
    int n = blockIdx.x;
    int t = threadIdx.x;
    float v[4]; float ss = 0.f;
#pragma unroll
    for (int i = 0; i < 4; i++) {
        int j = t + i * 256;
        v[i] = g_ssm[(size_t)n * DDIM + j] + g_moe[(size_t)n * DDIM + j];
        ss += v[i] * v[i];
    }
    ss = blockReduceSum(ss);
    float inv = 1.f / sqrtf(ss * (1.f / DDIM) + 1e-6f);
#pragma unroll
    for (int i = 0; i < 4; i++) {
        int j = t + i * 256;
        out[(size_t)n * DDIM + j] = nw[j] * v[i] * inv;
    }
}

// ---------------- launch ----------------
extern "C" void kernel_launch(void* const* d_in, const int* in_sizes, int n_in,
                              void* d_out, int out_size) {
    (void)in_sizes; (void)n_in; (void)out_size;
    const float* x        = (const float*)d_in[0];
    const float* A_log    = (const float*)d_in[1];
    const float* D_param  = (const float*)d_in[2];
    const float* W_delta  = (const float*)d_in[3];
    const float* b_delta  = (const float*)d_in[4];
    const float* W_B      = (const float*)d_in[5];
    const float* W_C      = (const float*)d_in[6];
    const float* W_router = (const float*)d_in[7];
    const float* Wg       = (const float*)d_in[8];
    const float* Wu       = (const float*)d_in[9];
    const float* Wd       = (const float*)d_in[10];
    const float* wn_exp   = (const float*)d_in[11];
    const float* norm_w   = (const float*)d_in[12];
    float* out = (float*)d_out;

    k_zero<<<1024, 256>>>();
    k_delta<<<dim3(32, 16), 256>>>(x, W_delta, b_delta);
    k_bc<<<512, 256>>>(x, W_B, W_C);
    k_scan<<<128, 256>>>(x, A_log, D_param);
    k_router<<<512, 256>>>(W_router);
    for (int e = 0; e < NEXP; e++) {
        k_gu<<<dim3(32, 32), 256>>>(e, Wg, Wu);
        k_rmsg<<<4096, 256>>>(e, wn_exp);
        k_down<<<dim3(32, 16), 256>>>(e, Wd);
    }
    k_final<<<4096, 256>>>(norm_w, out);
}

// round 5
// speedup vs baseline: 2.3788x; 2.3788x over previous
#include <cuda_runtime.h>
#include <cuda_bf16.h>
#include <math.h>

#define NTOK 4096
#define DDIM 1024
#define SDIM 16
#define NEXP 4
#define HDIM 2048
#define LSEQ 2048

// ---------------- scratch (static device globals; no allocation) ----------------
__device__ float g_delta[NTOK * DDIM];
__device__ float g_Bm[NTOK * SDIM];
__device__ float g_Cm[NTOK * SDIM];
__device__ float g_ssm[NTOK * DDIM];
__device__ float g_moe[NTOK * DDIM];
__device__ float g_G[NTOK * HDIM];
__device__ int   g_cnt[NEXP];
__device__ int   g_list[NEXP * NTOK];
__device__ float g_wgt[NEXP * NTOK];

// ---------------- helpers ----------------
__device__ __forceinline__ float softplusf(float z) {
    return fmaxf(z, 0.f) + log1pf(__expf(-fabsf(z)));
}

__device__ __forceinline__ float blockReduceSum(float v) {
    __shared__ float sh[9];
    int lane = threadIdx.x & 31, wid = threadIdx.x >> 5;
#pragma unroll
    for (int o = 16; o > 0; o >>= 1) v += __shfl_xor_sync(0xffffffffu, v, o);
    if (lane == 0) sh[wid] = v;
    __syncthreads();
    if (wid == 0) {
        float t = (lane < 8) ? sh[lane] : 0.f;
#pragma unroll
        for (int o = 4; o > 0; o >>= 1) t += __shfl_xor_sync(0xffffffffu, t, o);
        if (lane == 0) sh[8] = t;
    }
    __syncthreads();
    return sh[8];
}

// round-to-nearest bf16, returned as float
__device__ __forceinline__ float bf16_rn(float v) {
    return __bfloat162float(__float2bfloat16(v));
}
// pack two floats into bf16x2 word: lower half = e0, upper half = e1
__device__ __forceinline__ unsigned bf2(float e0, float e1) {
    unsigned r;
    asm("cvt.rn.bf16x2.f32 %0, %1, %2;" : "=r"(r) : "f"(e1), "f"(e0));
    return r;
}
__device__ __forceinline__ unsigned sptr(const void* p) {
    return (unsigned)__cvta_generic_to_shared(p);
}
__device__ __forceinline__ void ldmA(unsigned addr, unsigned& a0, unsigned& a1,
                                     unsigned& a2, unsigned& a3) {
    asm volatile("ldmatrix.sync.aligned.m8n8.x4.shared.b16 {%0,%1,%2,%3}, [%4];"
                 : "=r"(a0), "=r"(a1), "=r"(a2), "=r"(a3) : "r"(addr));
}
__device__ __forceinline__ void ldmB(unsigned addr, unsigned& b0, unsigned& b1) {
    asm volatile("ldmatrix.sync.aligned.m8n8.x2.trans.shared.b16 {%0,%1}, [%2];"
                 : "=r"(b0), "=r"(b1) : "r"(addr));
}
__device__ __forceinline__ void mma16816(float* c, const unsigned* a, unsigned b0, unsigned b1) {
    asm volatile("mma.sync.aligned.m16n8k16.row.col.f32.bf16.bf16.f32 "
                 "{%0,%1,%2,%3}, {%4,%5,%6,%7}, {%8,%9}, {%0,%1,%2,%3};"
                 : "+f"(c[0]), "+f"(c[1]), "+f"(c[2]), "+f"(c[3])
                 : "r"(a[0]), "r"(a[1]), "r"(a[2]), "r"(a[3]), "r"(b0), "r"(b1));
}

// ---------------- zero moe + counts ----------------
__global__ void k_zero() {
    int i = blockIdx.x * blockDim.x + threadIdx.x;
    int stride = gridDim.x * blockDim.x;
    for (int j = i; j < NTOK * DDIM; j += stride) g_moe[j] = 0.f;
    if (i < NEXP) g_cnt[i] = 0;
}

// ============================================================================
// bf16-split GEMM core (shared by all GEMM kernels via macros)
// BM=128, BN=128, BK=32, 256 threads = 8 warps (2x4), warp tile 64x32.
// D = Ah@Bh + Ah@Bl + Al@Bh  (fp32 accumulate)
// ============================================================================

#define GEMM_SMEM                                            \
    __shared__ __align__(16) unsigned short Ah[128][40];     \
    __shared__ __align__(16) unsigned short Al[128][40];     \
    __shared__ __align__(16) unsigned short Bh[32][136];     \
    __shared__ __align__(16) unsigned short Bl[32][136];

// load one 4-float chunk of A row into hi/lo smem at column kc (even)
#define A_STORE(vec, kc)                                                  \
    {                                                                     \
        float4 _v = (vec);                                                \
        float _h0 = bf16_rn(_v.x), _h1 = bf16_rn(_v.y);                   \
        float _h2 = bf16_rn(_v.z), _h3 = bf16_rn(_v.w);                   \
        *(unsigned*)&Ah[arow][(kc)]     = bf2(_h0, _h1);                  \
        *(unsigned*)&Ah[arow][(kc) + 2] = bf2(_h2, _h3);                  \
        *(unsigned*)&Al[arow][(kc)]     = bf2(_v.x - _h0, _v.y - _h1);    \
        *(unsigned*)&Al[arow][(kc) + 2] = bf2(_v.z - _h2, _v.w - _h3);    \
    }

#define B_STORE(vec, nc)                                                  \
    {                                                                     \
        float4 _v = (vec);                                                \
        float _h0 = bf16_rn(_v.x), _h1 = bf16_rn(_v.y);                   \
        float _h2 = bf16_rn(_v.z), _h3 = bf16_rn(_v.w);                   \
        *(unsigned*)&Bh[bkr][(nc)]     = bf2(_h0, _h1);                   \
        *(unsigned*)&Bh[bkr][(nc) + 2] = bf2(_h2, _h3);                   \
        *(unsigned*)&Bl[bkr][(nc)]     = bf2(_v.x - _h0, _v.y - _h1);     \
        *(unsigned*)&Bl[bkr][(nc) + 2] = bf2(_v.z - _h2, _v.w - _h3);     \
    }

// compute phase for one BK=32 chunk (2 k16 steps, 3 split passes)
#define GEMM_COMPUTE                                                          \
    _Pragma("unroll")                                                         \
    for (int ks = 0; ks < 2; ks++) {                                          \
        unsigned ah[4][4], al[4][4], bh[4][2], bl[4][2];                      \
        int acol = ks * 16 + (lane >> 4) * 8;                                 \
        int marow = wm * 64 + (lane & 15);                                    \
        _Pragma("unroll")                                                     \
        for (int mb = 0; mb < 4; mb++) {                                      \
            ldmA(sptr(&Ah[marow + mb * 16][acol]),                            \
                 ah[mb][0], ah[mb][1], ah[mb][2], ah[mb][3]);                 \
            ldmA(sptr(&Al[marow + mb * 16][acol]),                            \
                 al[mb][0], al[mb][1], al[mb][2], al[mb][3]);                 \
        }                                                                     \
        int bkrow = ks * 16 + (lane & 15);                                    \
        _Pragma("unroll")                                                     \
        for (int nb = 0; nb < 4; nb++) {                                      \
            int nc = wn * 32 + nb * 8;                                        \
            ldmB(sptr(&Bh[bkrow][nc]), bh[nb][0], bh[nb][1]);                 \
            ldmB(sptr(&Bl[bkrow][nc]), bl[nb][0], bl[nb][1]);                 \
        }                                                                     \
        _Pragma("unroll")                                                     \
        for (int mb = 0; mb < 4; mb++)                                        \
            _Pragma("unroll")                                                 \
            for (int nb = 0; nb < 4; nb++) {                                  \
                mma16816(acc[mb][nb], ah[mb], bh[nb][0], bh[nb][1]);          \
                mma16816(acc[mb][nb], ah[mb], bl[nb][0], bl[nb][1]);          \
                mma16816(acc[mb][nb], al[mb], bh[nb][0], bh[nb][1]);          \
            }                                                                 \
    }

// ---------------- delta GEMM: softplus(x @ W_delta + b) ----------------
__global__ void __launch_bounds__(256) k_delta(const float* __restrict__ x,
                                               const float* __restrict__ Wd,
                                               const float* __restrict__ bd) {
    GEMM_SMEM
    const int K = DDIM, N = DDIM;
    int tid = threadIdx.x, lane = tid & 31, wid = tid >> 5;
    int wm = wid >> 2, wn = wid & 3;
    int rowBase = blockIdx.x * 128, colBase = blockIdx.y * 128;
    float acc[4][4][4] = {};
    int arow = tid >> 1, akb = (tid & 1) * 16;
    int bkr = tid >> 3, bnb = (tid & 7) * 16;
    const float* Aptr = x + (size_t)(rowBase + arow) * K + akb;
    const float* Bptr = Wd + (size_t)bkr * N + colBase + bnb;
    for (int k0 = 0; k0 < K; k0 += 32) {
#pragma unroll
        for (int i = 0; i < 4; i++) A_STORE(*(const float4*)(Aptr + k0 + i * 4), akb + i * 4);
        const float* bp = Bptr + (size_t)k0 * N;
#pragma unroll
        for (int i = 0; i < 4; i++) B_STORE(*(const float4*)(bp + i * 4), bnb + i * 4);
        __syncthreads();
        GEMM_COMPUTE
        __syncthreads();
    }
    int g = lane >> 2, t = lane & 3;
#pragma unroll
    for (int mb = 0; mb < 4; mb++) {
        int r0 = rowBase + wm * 64 + mb * 16 + g;
#pragma unroll
        for (int nb = 0; nb < 4; nb++) {
            int c0 = colBase + wn * 32 + nb * 8 + t * 2;
            float b0 = bd[c0], b1 = bd[c0 + 1];
            g_delta[(size_t)r0 * N + c0]           = softplusf(acc[mb][nb][0] + b0);
            g_delta[(size_t)r0 * N + c0 + 1]       = softplusf(acc[mb][nb][1] + b1);
            g_delta[(size_t)(r0 + 8) * N + c0]     = softplusf(acc[mb][nb][2] + b0);
            g_delta[(size_t)(r0 + 8) * N + c0 + 1] = softplusf(acc[mb][nb][3] + b1);
        }
    }
}

// ---------------- gate GEMM (gathered rows): g_G = silu(X@Wg) ----------------
__global__ void __launch_bounds__(256) k_gate(int e, const float* __restrict__ Wg_all) {
    GEMM_SMEM
    const int K = DDIM, N = HDIM;
    int cnt = g_cnt[e];
    int rowBase = blockIdx.x * 128;
    if (rowBase >= cnt) return;
    const float* Bsrc = Wg_all + (size_t)e * DDIM * HDIM;
    int tid = threadIdx.x, lane = tid & 31, wid = tid >> 5;
    int wm = wid >> 2, wn = wid & 3;
    int colBase = blockIdx.y * 128;
    float acc[4][4][4] = {};
    int arow = tid >> 1, akb = (tid & 1) * 16;
    int bkr = tid >> 3, bnb = (tid & 7) * 16;
    int grow = rowBase + arow;
    int src = (grow < cnt) ? g_list[e * NTOK + grow] : g_list[e * NTOK];
    const float* Aptr = g_ssm + (size_t)src * K + akb;
    const float* Bptr = Bsrc + (size_t)bkr * N + colBase + bnb;
    for (int k0 = 0; k0 < K; k0 += 32) {
#pragma unroll
        for (int i = 0; i < 4; i++) A_STORE(*(const float4*)(Aptr + k0 + i * 4), akb + i * 4);
        const float* bp = Bptr + (size_t)k0 * N;
#pragma unroll
        for (int i = 0; i < 4; i++) B_STORE(*(const float4*)(bp + i * 4), bnb + i * 4);
        __syncthreads();
        GEMM_COMPUTE
        __syncthreads();
    }
    int g = lane >> 2, t = lane & 3;
#pragma unroll
    for (int mb = 0; mb < 4; mb++) {
        int r0 = rowBase + wm * 64 + mb * 16 + g;
#pragma unroll
        for (int nb = 0; nb < 4; nb++) {
            int c0 = colBase + wn * 32 + nb * 8 + t * 2;
            if (r0 < cnt) {
                float v0 = acc[mb][nb][0], v1 = acc[mb][nb][1];
                g_G[(size_t)r0 * N + c0]     = v0 / (1.f + __expf(-v0));
                g_G[(size_t)r0 * N + c0 + 1] = v1 / (1.f + __expf(-v1));
            }
            if (r0 + 8 < cnt) {
                float v2 = acc[mb][nb][2], v3 = acc[mb][nb][3];
                g_G[(size_t)(r0 + 8) * N + c0]     = v2 / (1.f + __expf(-v2));
                g_G[(size_t)(r0 + 8) * N + c0 + 1] = v3 / (1.f + __expf(-v3));
            }
        }
    }
}

// ---------------- up GEMM (gathered rows): g_G *= X@Wu ----------------
__global__ void __launch_bounds__(256) k_up(int e, const float* __restrict__ Wu_all) {
    GEMM_SMEM
    const int K = DDIM, N = HDIM;
    int cnt = g_cnt[e];
    int rowBase = blockIdx.x * 128;
    if (rowBase >= cnt) return;
    const float* Bsrc = Wu_all + (size_t)e * DDIM * HDIM;
    int tid = threadIdx.x, lane = tid & 31, wid = tid >> 5;
    int wm = wid >> 2, wn = wid & 3;
    int colBase = blockIdx.y * 128;
    float acc[4][4][4] = {};
    int arow = tid >> 1, akb = (tid & 1) * 16;
    int bkr = tid >> 3, bnb = (tid & 7) * 16;
    int grow = rowBase + arow;
    int src = (grow < cnt) ? g_list[e * NTOK + grow] : g_list[e * NTOK];
    const float* Aptr = g_ssm + (size_t)src * K + akb;
    const float* Bptr = Bsrc + (size_t)bkr * N + colBase + bnb;
    for (int k0 = 0; k0 < K; k0 += 32) {
#pragma unroll
        for (int i = 0; i < 4; i++) A_STORE(*(const float4*)(Aptr + k0 + i * 4), akb + i * 4);
        const float* bp = Bptr + (size_t)k0 * N;
#pragma unroll
        for (int i = 0; i < 4; i++) B_STORE(*(const float4*)(bp + i * 4), bnb + i * 4);
        __syncthreads();
        GEMM_COMPUTE
        __syncthreads();
    }
    int g = lane >> 2, t = lane & 3;
#pragma unroll
    for (int mb = 0; mb < 4; mb++) {
        int r0 = rowBase + wm * 64 + mb * 16 + g;
#pragma unroll
        for (int nb = 0; nb < 4; nb++) {
            int c0 = colBase + wn * 32 + nb * 8 + t * 2;
            if (r0 < cnt) {
                g_G[(size_t)r0 * N + c0]     *= acc[mb][nb][0];
                g_G[(size_t)r0 * N + c0 + 1] *= acc[mb][nb][1];
            }
            if (r0 + 8 < cnt) {
                g_G[(size_t)(r0 + 8) * N + c0]     *= acc[mb][nb][2];
                g_G[(size_t)(r0 + 8) * N + c0 + 1] *= acc[mb][nb][3];
            }
        }
    }
}

// ---------------- down GEMM + weighted scatter-add ----------------
__global__ void __launch_bounds__(256) k_down(int e, const float* __restrict__ Wd_all) {
    GEMM_SMEM
    const int K = HDIM, N = DDIM;
    int cnt = g_cnt[e];
    int rowBase = blockIdx.x * 128;
    if (rowBase >= cnt) return;
    const float* Bsrc = Wd_all + (size_t)e * HDIM * DDIM;
    int tid = threadIdx.x, lane = tid & 31, wid = tid >> 5;
    int wm = wid >> 2, wn = wid & 3;
    int colBase = blockIdx.y * 128;
    float acc[4][4][4] = {};
    int arow = tid >> 1, akb = (tid & 1) * 16;
    int bkr = tid >> 3, bnb = (tid & 7) * 16;
    const float* Aptr = g_G + (size_t)(rowBase + arow) * K + akb;
    const float* Bptr = Bsrc + (size_t)bkr * N + colBase + bnb;
    for (int k0 = 0; k0 < K; k0 += 32) {
#pragma unroll
        for (int i = 0; i < 4; i++) A_STORE(*(const float4*)(Aptr + k0 + i * 4), akb + i * 4);
        const float* bp = Bptr + (size_t)k0 * N;
#pragma unroll
        for (int i = 0; i < 4; i++) B_STORE(*(const float4*)(bp + i * 4), bnb + i * 4);
        __syncthreads();
        GEMM_COMPUTE
        __syncthreads();
    }
    int g = lane >> 2, t = lane & 3;
#pragma unroll
    for (int mb = 0; mb < 4; mb++) {
        int r0 = rowBase + wm * 64 + mb * 16 + g;
#pragma unroll
        for (int nb = 0; nb < 4; nb++) {
            int c0 = colBase + wn * 32 + nb * 8 + t * 2;
            if (r0 < cnt) {
                int tok = g_list[e * NTOK + r0];
                float w = g_wgt[e * NTOK + r0];
                g_moe[(size_t)tok * N + c0]     += w * acc[mb][nb][0];
                g_moe[(size_t)tok * N + c0 + 1] += w * acc[mb][nb][1];
            }
            if (r0 + 8 < cnt) {
                int tok = g_list[e * NTOK + r0 + 8];
                float w = g_wgt[e * NTOK + r0 + 8];
                g_moe[(size_t)tok * N + c0]     += w * acc[mb][nb][2];
                g_moe[(size_t)tok * N + c0 + 1] += w * acc[mb][nb][3];
            }
        }
    }
}

// ---------------- Bm / Cm: skinny GEMM, one warp per token ----------------
__global__ void k_bc(const float* __restrict__ x, const float* __restrict__ WB,
                     const float* __restrict__ WC) {
    int wid = (blockIdx.x * blockDim.x + threadIdx.x) >> 5;
    int lane = threadIdx.x & 31;
    if (wid >= NTOK) return;
    const float* W = (lane < 16) ? WB : WC;
    int col = lane & 15;
    const float* xr = x + (size_t)wid * DDIM;
    float acc = 0.f;
#pragma unroll 8
    for (int k = 0; k < DDIM; k++) acc = fmaf(xr[k], W[k * SDIM + col], acc);
    if (lane < 16) g_Bm[wid * SDIM + col] = acc;
    else           g_Cm[wid * SDIM + col] = acc;
}

// ---------------- selective scan: 16 lanes (states) per (b,d) channel ----------------
__global__ void k_scan(const float* __restrict__ x, const float* __restrict__ A_log,
                       const float* __restrict__ Dp) {
    int tid = threadIdx.x;
    int grp = tid >> 4, s = tid & 15;
    int c = blockIdx.x * 16 + grp;
    int b = c >> 10, d = c & 1023;
    float a = -__expf(A_log[d * SDIM + s]);
    float dpar = Dp[d];
    float h = 0.f;
    const float* xb = x + (size_t)b * LSEQ * DDIM + d;
    const float* db = g_delta + (size_t)b * LSEQ * DDIM + d;
    const float* Bb = g_Bm + (size_t)b * LSEQ * SDIM + s;
    const float* Cb = g_Cm + (size_t)b * LSEQ * SDIM + s;
    float* yb = g_ssm + (size_t)b * LSEQ * DDIM + d;
#pragma unroll 4
    for (int t = 0; t < LSEQ; t++) {
        float dv = db[(size_t)t * DDIM];
        float xv = xb[(size_t)t * DDIM];
        float Bv = Bb[t * SDIM];
        float Cv = Cb[t * SDIM];
        float barA = __expf(fminf(dv * a, 10.f));
        float barB = fminf(fmaxf(dv * Bv, -10.f), 10.f);
        h = fminf(fmaxf(fmaf(barA, h, barB * xv), -10000.f), 10000.f);
        float p = h * Cv;
        p += __shfl_xor_sync(0xffffffffu, p, 8);
        p += __shfl_xor_sync(0xffffffffu, p, 4);
        p += __shfl_xor_sync(0xffffffffu, p, 2);
        p += __shfl_xor_sync(0xffffffffu, p, 1);
        if (s == 0) yb[(size_t)t * DDIM] = p + xv * dpar;
    }
}

// ---------------- router: softmax over E=4, top-2, build per-expert lists ----------------
__global__ void k_router(const float* __restrict__ Wr) {
    int wid = (blockIdx.x * blockDim.x + threadIdx.x) >> 5;
    int lane = threadIdx.x & 31;
    if (wid >= NTOK) return;
    const float* xr = g_ssm + (size_t)wid * DDIM;
    float l[4] = {0.f, 0.f, 0.f, 0.f};
    for (int k = lane; k < DDIM; k += 32) {
        float xv = xr[k];
        float4 w = *(const float4*)(Wr + (size_t)k * 4);
        l[0] = fmaf(xv, w.x, l[0]);
        l[1] = fmaf(xv, w.y, l[1]);
        l[2] = fmaf(xv, w.z, l[2]);
        l[3] = fmaf(xv, w.w, l[3]);
    }
#pragma unroll
    for (int e = 0; e < 4; e++)
#pragma unroll
        for (int o = 16; o > 0; o >>= 1) l[e] += __shfl_xor_sync(0xffffffffu, l[e], o);
    if (lane == 0) {
        float m = fmaxf(fmaxf(l[0], l[1]), fmaxf(l[2], l[3]));
        float p[4]; float ssum = 0.f;
#pragma unroll
        for (int e = 0; e < 4; e++) { p[e] = __expf(l[e] - m); ssum += p[e]; }
#pragma unroll
        for (int e = 0; e < 4; e++) p[e] /= ssum;
        int e1 = 0; float b1 = p[0];
#pragma unroll
        for (int e = 1; e < 4; e++) if (p[e] > b1) { b1 = p[e]; e1 = e; }
        int e2 = -1; float b2 = -1.f;
#pragma unroll
        for (int e = 0; e < 4; e++) if (e != e1 && p[e] > b2) { b2 = p[e]; e2 = e; }
        float wsum = b1 + b2 + 1e-9f;
        float w1 = b1 / wsum, w2 = b2 / wsum;
        int pos1 = atomicAdd(&g_cnt[e1], 1);
        g_list[e1 * NTOK + pos1] = wid; g_wgt[e1 * NTOK + pos1] = w1;
        int pos2 = atomicAdd(&g_cnt[e2], 1);
        g_list[e2 * NTOK + pos2] = wid; g_wgt[e2 * NTOK + pos2] = w2;
    }
}

// ---------------- rmsnorm over expert hidden rows ----------------
__global__ void k_rmsg(int e, const float* __restrict__ wn) {
    int m = blockIdx.x;
    if (m >= g_cnt[e]) return;
    float* row = g_G + (size_t)m * HDIM;
    const float* w = wn + (size_t)e * HDIM;
    float v[8]; float ss = 0.f;
#pragma unroll
    for (int i = 0; i < 8; i++) {
        v[i] = row[threadIdx.x + i * 256];
        ss += v[i] * v[i];
    }
    ss = blockReduceSum(ss);
    float inv = 1.f / sqrtf(ss * (1.f / HDIM) + 1e-6f);
#pragma unroll
    for (int i = 0; i < 8; i++)
        row[threadIdx.x + i * 256] = w[threadIdx.x + i * 256] * v[i] * inv;
}

// ---------------- final rmsnorm(ssm + moe) ----------------
__global__ void k_final(const float* __restrict__ nw, float* __restrict__ out) {
    int n = blockIdx.x;
    int t = threadIdx.x;
    float v[4]; float ss = 0.f;
#pragma unroll
    for (int i = 0; i < 4; i++) {
        int j = t + i * 256;
        v[i] = g_ssm[(size_t)n * DDIM + j] + g_moe[(size_t)n * DDIM + j];
        ss += v[i] * v[i];
    }
    ss = blockReduceSum(ss);
    float inv = 1.f / sqrtf(ss * (1.f / DDIM) + 1e-6f);
#pragma unroll
    for (int i = 0; i < 4; i++) {
        int j = t + i * 256;
        out[(size_t)n * DDIM + j] = nw[j] * v[i] * inv;
    }
}

// ---------------- launch ----------------
extern "C" void kernel_launch(void* const* d_in, const int* in_sizes, int n_in,
                              void* d_out, int out_size) {
    (void)in_sizes; (void)n_in; (void)out_size;
    const float* x        = (const float*)d_in[0];
    const float* A_log    = (const float*)d_in[1];
    const float* D_param  = (const float*)d_in[2];
    const float* W_delta  = (const float*)d_in[3];
    const float* b_delta  = (const float*)d_in[4];
    const float* W_B      = (const float*)d_in[5];
    const float* W_C      = (const float*)d_in[6];
    const float* W_router = (const float*)d_in[7];
    const float* Wg       = (const float*)d_in[8];
    const float* Wu       = (const float*)d_in[9];
    const float* Wd       = (const float*)d_in[10];
    const float* wn_exp   = (const float*)d_in[11];
    const float* norm_w   = (const float*)d_in[12];
    float* out = (float*)d_out;

    k_zero<<<1024, 256>>>();
    k_delta<<<dim3(32, 8), 256>>>(x, W_delta, b_delta);
    k_bc<<<512, 256>>>(x, W_B, W_C);
    k_scan<<<128, 256>>>(x, A_log, D_param);
    k_router<<<512, 256>>>(W_router);
    for (int e = 0; e < NEXP; e++) {
        k_gate<<<dim3(32, 16), 256>>>(e, Wg);
        k_up<<<dim3(32, 16), 256>>>(e, Wu);
        k_rmsg<<<4096, 256>>>(e, wn_exp);
        k_down<<<dim3(32, 8), 256>>>(e, Wd);
    }
    k_final<<<4096, 256>>>(norm_w, out);
}